// round 10
// baseline (speedup 1.0000x reference)
#include <cuda_runtime.h>
#include <cuda_fp16.h>
#include <cstdint>

#define N_USERS 100000
#define N_ITEMS 50000
#define N_NODES 150000
#define EMB     128
#define NNZ     1600000
#define BATCH   4096
#define CAP     64            /* bucket capacity per row; Poisson(10.7) -> safe */

#define TOTAL4   (N_NODES * EMB / 4)

// ---------------- device scratch (no allocations allowed) ------------------
__device__ __half g_x16[N_NODES * EMB];        // fp16 concat(user_emb,item_emb)
__device__ __half g_h1 [N_NODES * EMB];        // layer 1 out (fp16)
__device__ __half g_h2 [N_NODES * EMB];        // layer 2 out (fp16)
__device__ int2   g_bucket[N_NODES * CAP];     // {col, float_bits(val)} per row
__device__ int    g_cnt[N_NODES];              // per-row edge count (cursor)
__device__ unsigned char g_mark[N_NODES];      // 1 = h2 needed at this node
__device__ int    g_is64;

// ---------------------------------------------------------------------------
// Convert inputs -> fp16 concat buffer; first threads also zero cnt + mark.
// ---------------------------------------------------------------------------
__global__ void k_convert(const float4* __restrict__ u, const float4* __restrict__ it) {
    int i = blockIdx.x * blockDim.x + threadIdx.x;
    if (i < N_NODES) { g_cnt[i] = 0; g_mark[i] = 0; }
    if (i >= TOTAL4) return;
    const int usplit = N_USERS * EMB / 4;
    float4 v = (i < usplit) ? __ldg(&u[i]) : __ldg(&it[i - usplit]);
    __half2 h0 = __floats2half2_rn(v.x, v.y);
    __half2 h1 = __floats2half2_rn(v.z, v.w);
    uint2 p;
    p.x = *(const unsigned*)&h0;
    p.y = *(const unsigned*)&h1;
    ((uint2*)g_x16)[i] = p;
}

// ---------------------------------------------------------------------------
// Single-pass edge binning: bucket[row][cursor++] = {col, val}
// ---------------------------------------------------------------------------
__global__ void k_scatter(const int* __restrict__ rows,
                          const int* __restrict__ cols,
                          const float* __restrict__ vals) {
    int i = blockIdx.x * blockDim.x + threadIdx.x;
    if (i >= NNZ) return;
    int r = __ldg(&rows[i]);
    int p = atomicAdd(&g_cnt[r], 1);
    if (p < CAP)
        g_bucket[(size_t)r * CAP + p] =
            make_int2(__ldg(&cols[i]), __float_as_int(__ldg(&vals[i])));
}

// ---------------------------------------------------------------------------
// Mark the nodes where h2 is actually read: batch nodes + their edge columns.
// ONE WARP PER OUTPUT ROW (needs 2*BATCH warps!); lanes split the bucket.
// ---------------------------------------------------------------------------
__global__ void k_mark(const void* __restrict__ users,
                       const void* __restrict__ items) {
    int warp = (blockIdx.x * blockDim.x + threadIdx.x) >> 5;
    if (warp >= 2 * BATCH) return;
    int lane = threadIdx.x & 31;

    long long node;
    if (warp < BATCH) {
        node = g_is64 ? ((const long long*)users)[warp]
                      : (long long)((const int*)users)[warp];
    } else {
        int j = warp - BATCH;
        long long iv = g_is64 ? ((const long long*)items)[j]
                              : (long long)((const int*)items)[j];
        node = (long long)N_USERS + iv;
    }
    if (lane == 0) g_mark[node] = 1;
    int n = min(__ldg(&g_cnt[node]), CAP);
    const int2* eb = g_bucket + (size_t)node * CAP;
    for (int j = lane; j < n; j += 32)
        g_mark[__ldg(&eb[j]).x] = 1;
}

// ---------------------------------------------------------------------------
// SpMM (fp16 gather, fp32 accumulate): dst[row] = sum v * src16[col]
// Two rows per warp, 16 lanes/row, lane owns 8 dims (uint4 = 4 half2).
// which: 0 = x16 -> h1 (all rows), 1 = h1 -> h2 (marked rows only)
// ---------------------------------------------------------------------------
__global__ void k_spmm16(int which) {
    int warp = (blockIdx.x * blockDim.x + threadIdx.x) >> 5;
    int lane = threadIdx.x & 31;
    int hid  = lane >> 4;
    int sub  = lane & 15;
    int row  = warp * 2 + hid;
    if (row >= N_NODES) return;
    if (which && !g_mark[row]) return;          // prune unneeded h2 rows

    const uint4* x = which ? (const uint4*)g_h1 : (const uint4*)g_x16;
    uint4*       y = which ? (uint4*)g_h2       : (uint4*)g_h1;

    int n = min(__ldg(&g_cnt[row]), CAP);
    const int2* eb = g_bucket + (size_t)row * CAP;

    float4 a0 = make_float4(0.f, 0.f, 0.f, 0.f);
    float4 a1 = make_float4(0.f, 0.f, 0.f, 0.f);
    #pragma unroll 4
    for (int j = 0; j < n; j++) {
        int2  cv = __ldg(&eb[j]);
        float v  = __int_as_float(cv.y);
        uint4 xv = __ldg(x + (size_t)cv.x * 16 + sub);
        float2 f0 = __half22float2(*(const __half2*)&xv.x);
        float2 f1 = __half22float2(*(const __half2*)&xv.y);
        float2 f2 = __half22float2(*(const __half2*)&xv.z);
        float2 f3 = __half22float2(*(const __half2*)&xv.w);
        a0.x = fmaf(v, f0.x, a0.x);  a0.y = fmaf(v, f0.y, a0.y);
        a0.z = fmaf(v, f1.x, a0.z);  a0.w = fmaf(v, f1.y, a0.w);
        a1.x = fmaf(v, f2.x, a1.x);  a1.y = fmaf(v, f2.y, a1.y);
        a1.z = fmaf(v, f3.x, a1.z);  a1.w = fmaf(v, f3.y, a1.w);
    }
    __half2 h0 = __floats2half2_rn(a0.x, a0.y);
    __half2 h1 = __floats2half2_rn(a0.z, a0.w);
    __half2 h2 = __floats2half2_rn(a1.x, a1.y);
    __half2 h3 = __floats2half2_rn(a1.z, a1.w);
    uint4 o;
    o.x = *(const unsigned*)&h0;
    o.y = *(const unsigned*)&h1;
    o.z = *(const unsigned*)&h2;
    o.w = *(const unsigned*)&h3;
    y[(size_t)row * 16 + sub] = o;
}

// ---------------------------------------------------------------------------
// Index-dtype detection (int64 vs int32 users buffer)
// ---------------------------------------------------------------------------
__global__ void k_detect(const unsigned* __restrict__ w) {
    __shared__ unsigned s;
    if (threadIdx.x == 0) s = 0u;
    __syncthreads();
    unsigned o = 0u;
    for (int i = 1 + 2 * threadIdx.x; i < BATCH; i += 2 * blockDim.x)
        o |= w[i];
    atomicOr(&s, o);
    __syncthreads();
    if (threadIdx.x == 0) g_is64 = (s == 0u) ? 1 : 0;
}

// ---------------------------------------------------------------------------
// Fused layer-3 + mean + gather. Two output rows per warp, fp32 math:
//   out[r] = (b0_fp32[node] + h1[node] + h2[node] + sum v*h2[col]) / 4
// ---------------------------------------------------------------------------
__global__ void k_fused_out(const void* __restrict__ users,
                            const void* __restrict__ items,
                            const float4* __restrict__ uemb,
                            const float4* __restrict__ iemb,
                            float4* __restrict__ out) {
    int warp = (blockIdx.x * blockDim.x + threadIdx.x) >> 5;
    int lane = threadIdx.x & 31;
    int hid  = lane >> 4;
    int sub  = lane & 15;
    int r    = warp * 2 + hid;
    if (r >= 2 * BATCH) return;

    long long node;
    if (r < BATCH) {
        node = g_is64 ? ((const long long*)users)[r]
                      : (long long)((const int*)users)[r];
    } else {
        int j = r - BATCH;
        long long iv = g_is64 ? ((const long long*)items)[j]
                              : (long long)((const int*)items)[j];
        node = (long long)N_USERS + iv;
    }

    const uint4* h1 = (const uint4*)g_h1;
    const uint4* h2 = (const uint4*)g_h2;

    const float4* b0base = (node < N_USERS) ? (uemb + node * 32)
                                            : (iemb + (node - N_USERS) * 32);
    float4 a0 = __ldg(b0base + sub * 2);
    float4 a1 = __ldg(b0base + sub * 2 + 1);

    {
        uint4 a = __ldg(h1 + node * 16 + sub);
        uint4 b = __ldg(h2 + node * 16 + sub);
        float2 p;
        p = __half22float2(*(const __half2*)&a.x); a0.x += p.x; a0.y += p.y;
        p = __half22float2(*(const __half2*)&a.y); a0.z += p.x; a0.w += p.y;
        p = __half22float2(*(const __half2*)&a.z); a1.x += p.x; a1.y += p.y;
        p = __half22float2(*(const __half2*)&a.w); a1.z += p.x; a1.w += p.y;
        p = __half22float2(*(const __half2*)&b.x); a0.x += p.x; a0.y += p.y;
        p = __half22float2(*(const __half2*)&b.y); a0.z += p.x; a0.w += p.y;
        p = __half22float2(*(const __half2*)&b.z); a1.x += p.x; a1.y += p.y;
        p = __half22float2(*(const __half2*)&b.w); a1.z += p.x; a1.w += p.y;
    }

    int n = min(__ldg(&g_cnt[node]), CAP);
    const int2* eb = g_bucket + (size_t)node * CAP;
    #pragma unroll 4
    for (int j = 0; j < n; j++) {
        int2  cv = __ldg(&eb[j]);
        float v  = __int_as_float(cv.y);
        uint4 xv = __ldg(h2 + (size_t)cv.x * 16 + sub);
        float2 f0 = __half22float2(*(const __half2*)&xv.x);
        float2 f1 = __half22float2(*(const __half2*)&xv.y);
        float2 f2 = __half22float2(*(const __half2*)&xv.z);
        float2 f3 = __half22float2(*(const __half2*)&xv.w);
        a0.x = fmaf(v, f0.x, a0.x);  a0.y = fmaf(v, f0.y, a0.y);
        a0.z = fmaf(v, f1.x, a0.z);  a0.w = fmaf(v, f1.y, a0.w);
        a1.x = fmaf(v, f2.x, a1.x);  a1.y = fmaf(v, f2.y, a1.y);
        a1.z = fmaf(v, f3.x, a1.z);  a1.w = fmaf(v, f3.y, a1.w);
    }

    a0.x *= 0.25f; a0.y *= 0.25f; a0.z *= 0.25f; a0.w *= 0.25f;
    a1.x *= 0.25f; a1.y *= 0.25f; a1.z *= 0.25f; a1.w *= 0.25f;
    out[(size_t)r * 32 + sub * 2]     = a0;
    out[(size_t)r * 32 + sub * 2 + 1] = a1;
}

// ---------------------------------------------------------------------------
extern "C" void kernel_launch(void* const* d_in, const int* in_sizes, int n_in,
                              void* d_out, int out_size) {
    const float4* user_emb = (const float4*)d_in[0];
    const float4* item_emb = (const float4*)d_in[1];
    const float*  adj_vals = (const float*)d_in[2];
    const int*    adj_rows = (const int*)d_in[3];
    const int*    adj_cols = (const int*)d_in[4];
    const void*   users    = d_in[5];
    const void*   items    = d_in[6];
    float4*       out      = (float4*)d_out;

    const int NNZ_BLOCKS  = (NNZ + 255) / 256;
    const int EW_BLOCKS   = (TOTAL4 + 255) / 256;
    const int SPMM_BLOCKS = (N_NODES / 2 * 32 + 255) / 256;   // 2 rows per warp
    const int OUT_BLOCKS  = (BATCH * 32 + 255) / 256;          // 2 out rows per warp
    const int MARK_BLOCKS = (2 * BATCH * 32 + 255) / 256;      // 1 row per warp!

    k_detect<<<1, 256>>>((const unsigned*)users);
    k_convert<<<EW_BLOCKS, 256>>>(user_emb, item_emb);
    k_scatter<<<NNZ_BLOCKS, 256>>>(adj_rows, adj_cols, adj_vals);
    k_mark<<<MARK_BLOCKS, 256>>>(users, items);
    k_spmm16<<<SPMM_BLOCKS, 256>>>(0);
    k_spmm16<<<SPMM_BLOCKS, 256>>>(1);
    k_fused_out<<<OUT_BLOCKS, 256>>>(users, items, user_emb, item_emb, out);
}

// round 12
// speedup vs baseline: 1.1411x; 1.1411x over previous
#include <cuda_runtime.h>
#include <cuda_fp16.h>
#include <cstdint>

#define N_USERS 100000
#define N_ITEMS 50000
#define N_NODES 150000
#define EMB     128
#define NNZ     1600000
#define BATCH   4096
#define CAP     64            /* bucket capacity per row; Poisson(10.7) -> safe */

#define TOTAL4   (N_NODES * EMB / 4)
#define EW_BLOCKS   ((TOTAL4 + 255) / 256)        /* 18750 convert blocks */
#define NNZ_BLOCKS  ((NNZ + 255) / 256)           /* 6250 scatter blocks  */
#define CNT_BLOCKS  ((N_NODES + 255) / 256)       /* 586 zeroing blocks   */

// ---------------- device scratch (no allocations allowed) ------------------
__device__ __half g_x16[N_NODES * EMB];        // fp16 concat(user_emb,item_emb)
__device__ __half g_h1 [N_NODES * EMB];        // layer 1 out (fp16)
__device__ __half g_h2 [N_NODES * EMB];        // layer 2 out (fp16)
__device__ int2   g_bucket[N_NODES * CAP];     // {col, float_bits(val)} per row
__device__ int    g_cnt[N_NODES];              // per-row edge count (cursor)
__device__ int    g_is64;

// ---------------------------------------------------------------------------
// Prep: block 0 detects index dtype; remaining blocks zero the edge cursors.
// ---------------------------------------------------------------------------
__global__ void k_prep(const unsigned* __restrict__ w) {
    if (blockIdx.x == 0) {
        __shared__ unsigned s;
        if (threadIdx.x == 0) s = 0u;
        __syncthreads();
        unsigned o = 0u;
        for (int i = 1 + 2 * threadIdx.x; i < BATCH; i += 2 * blockDim.x)
            o |= w[i];
        atomicOr(&s, o);
        __syncthreads();
        if (threadIdx.x == 0) g_is64 = (s == 0u) ? 1 : 0;
    } else {
        int i = (blockIdx.x - 1) * blockDim.x + threadIdx.x;
        if (i < N_NODES) g_cnt[i] = 0;
    }
}

// ---------------------------------------------------------------------------
// Fused convert + scatter (independent data; overlapped memory streams).
// Blocks [0, EW_BLOCKS): convert inputs -> fp16 concat buffer.
// Blocks [EW_BLOCKS, EW_BLOCKS+NNZ_BLOCKS): bin edges into row buckets.
// ---------------------------------------------------------------------------
__global__ void k_conv_scatter(const float4* __restrict__ u,
                               const float4* __restrict__ it,
                               const int*   __restrict__ rows,
                               const int*   __restrict__ cols,
                               const float* __restrict__ vals) {
    if (blockIdx.x < EW_BLOCKS) {
        int i = blockIdx.x * blockDim.x + threadIdx.x;
        if (i >= TOTAL4) return;
        const int usplit = N_USERS * EMB / 4;
        float4 v = (i < usplit) ? __ldg(&u[i]) : __ldg(&it[i - usplit]);
        __half2 h0 = __floats2half2_rn(v.x, v.y);
        __half2 h1 = __floats2half2_rn(v.z, v.w);
        uint2 p;
        p.x = *(const unsigned*)&h0;
        p.y = *(const unsigned*)&h1;
        ((uint2*)g_x16)[i] = p;
    } else {
        int i = (blockIdx.x - EW_BLOCKS) * blockDim.x + threadIdx.x;
        if (i >= NNZ) return;
        int r = __ldg(&rows[i]);
        int p = atomicAdd(&g_cnt[r], 1);
        if (p < CAP)
            g_bucket[(size_t)r * CAP + p] =
                make_int2(__ldg(&cols[i]), __float_as_int(__ldg(&vals[i])));
    }
}

// ---------------------------------------------------------------------------
// SpMM (fp16 gather, fp32 accumulate): dst[row] = sum v * src16[col]
// Two rows per warp, 16 lanes/row, lane owns 8 dims (uint4 = 4 half2).
// which: 0 = x16 -> h1, 1 = h1 -> h2
// ---------------------------------------------------------------------------
__global__ void k_spmm16(int which) {
    int warp = (blockIdx.x * blockDim.x + threadIdx.x) >> 5;
    int lane = threadIdx.x & 31;
    int hid  = lane >> 4;
    int sub  = lane & 15;
    int row  = warp * 2 + hid;
    if (row >= N_NODES) return;

    const uint4* x = which ? (const uint4*)g_h1 : (const uint4*)g_x16;
    uint4*       y = which ? (uint4*)g_h2       : (uint4*)g_h1;

    int n = min(__ldg(&g_cnt[row]), CAP);
    const int2* eb = g_bucket + (size_t)row * CAP;

    float4 a0 = make_float4(0.f, 0.f, 0.f, 0.f);
    float4 a1 = make_float4(0.f, 0.f, 0.f, 0.f);
    #pragma unroll 4
    for (int j = 0; j < n; j++) {
        int2  cv = __ldg(&eb[j]);
        float v  = __int_as_float(cv.y);
        uint4 xv = __ldg(x + (size_t)cv.x * 16 + sub);
        float2 f0 = __half22float2(*(const __half2*)&xv.x);
        float2 f1 = __half22float2(*(const __half2*)&xv.y);
        float2 f2 = __half22float2(*(const __half2*)&xv.z);
        float2 f3 = __half22float2(*(const __half2*)&xv.w);
        a0.x = fmaf(v, f0.x, a0.x);  a0.y = fmaf(v, f0.y, a0.y);
        a0.z = fmaf(v, f1.x, a0.z);  a0.w = fmaf(v, f1.y, a0.w);
        a1.x = fmaf(v, f2.x, a1.x);  a1.y = fmaf(v, f2.y, a1.y);
        a1.z = fmaf(v, f3.x, a1.z);  a1.w = fmaf(v, f3.y, a1.w);
    }
    __half2 h0 = __floats2half2_rn(a0.x, a0.y);
    __half2 h1 = __floats2half2_rn(a0.z, a0.w);
    __half2 h2 = __floats2half2_rn(a1.x, a1.y);
    __half2 h3 = __floats2half2_rn(a1.z, a1.w);
    uint4 o;
    o.x = *(const unsigned*)&h0;
    o.y = *(const unsigned*)&h1;
    o.z = *(const unsigned*)&h2;
    o.w = *(const unsigned*)&h3;
    y[(size_t)row * 16 + sub] = o;
}

// ---------------------------------------------------------------------------
// Fused layer-3 + mean + gather. Two output rows per warp, fp32 math:
//   out[r] = (b0_fp32[node] + h1[node] + h2[node] + sum v*h2[col]) / 4
// ---------------------------------------------------------------------------
__global__ void k_fused_out(const void* __restrict__ users,
                            const void* __restrict__ items,
                            const float4* __restrict__ uemb,
                            const float4* __restrict__ iemb,
                            float4* __restrict__ out) {
    int warp = (blockIdx.x * blockDim.x + threadIdx.x) >> 5;
    int lane = threadIdx.x & 31;
    int hid  = lane >> 4;
    int sub  = lane & 15;
    int r    = warp * 2 + hid;
    if (r >= 2 * BATCH) return;

    long long node;
    if (r < BATCH) {
        node = g_is64 ? ((const long long*)users)[r]
                      : (long long)((const int*)users)[r];
    } else {
        int j = r - BATCH;
        long long iv = g_is64 ? ((const long long*)items)[j]
                              : (long long)((const int*)items)[j];
        node = (long long)N_USERS + iv;
    }

    const uint4* h1 = (const uint4*)g_h1;
    const uint4* h2 = (const uint4*)g_h2;

    const float4* b0base = (node < N_USERS) ? (uemb + node * 32)
                                            : (iemb + (node - N_USERS) * 32);
    float4 a0 = __ldg(b0base + sub * 2);
    float4 a1 = __ldg(b0base + sub * 2 + 1);

    {
        uint4 a = __ldg(h1 + node * 16 + sub);
        uint4 b = __ldg(h2 + node * 16 + sub);
        float2 p;
        p = __half22float2(*(const __half2*)&a.x); a0.x += p.x; a0.y += p.y;
        p = __half22float2(*(const __half2*)&a.y); a0.z += p.x; a0.w += p.y;
        p = __half22float2(*(const __half2*)&a.z); a1.x += p.x; a1.y += p.y;
        p = __half22float2(*(const __half2*)&a.w); a1.z += p.x; a1.w += p.y;
        p = __half22float2(*(const __half2*)&b.x); a0.x += p.x; a0.y += p.y;
        p = __half22float2(*(const __half2*)&b.y); a0.z += p.x; a0.w += p.y;
        p = __half22float2(*(const __half2*)&b.z); a1.x += p.x; a1.y += p.y;
        p = __half22float2(*(const __half2*)&b.w); a1.z += p.x; a1.w += p.y;
    }

    int n = min(__ldg(&g_cnt[node]), CAP);
    const int2* eb = g_bucket + (size_t)node * CAP;
    #pragma unroll 4
    for (int j = 0; j < n; j++) {
        int2  cv = __ldg(&eb[j]);
        float v  = __int_as_float(cv.y);
        uint4 xv = __ldg(h2 + (size_t)cv.x * 16 + sub);
        float2 f0 = __half22float2(*(const __half2*)&xv.x);
        float2 f1 = __half22float2(*(const __half2*)&xv.y);
        float2 f2 = __half22float2(*(const __half2*)&xv.z);
        float2 f3 = __half22float2(*(const __half2*)&xv.w);
        a0.x = fmaf(v, f0.x, a0.x);  a0.y = fmaf(v, f0.y, a0.y);
        a0.z = fmaf(v, f1.x, a0.z);  a0.w = fmaf(v, f1.y, a0.w);
        a1.x = fmaf(v, f2.x, a1.x);  a1.y = fmaf(v, f2.y, a1.y);
        a1.z = fmaf(v, f3.x, a1.z);  a1.w = fmaf(v, f3.y, a1.w);
    }

    a0.x *= 0.25f; a0.y *= 0.25f; a0.z *= 0.25f; a0.w *= 0.25f;
    a1.x *= 0.25f; a1.y *= 0.25f; a1.z *= 0.25f; a1.w *= 0.25f;
    out[(size_t)r * 32 + sub * 2]     = a0;
    out[(size_t)r * 32 + sub * 2 + 1] = a1;
}

// ---------------------------------------------------------------------------
extern "C" void kernel_launch(void* const* d_in, const int* in_sizes, int n_in,
                              void* d_out, int out_size) {
    const float4* user_emb = (const float4*)d_in[0];
    const float4* item_emb = (const float4*)d_in[1];
    const float*  adj_vals = (const float*)d_in[2];
    const int*    adj_rows = (const int*)d_in[3];
    const int*    adj_cols = (const int*)d_in[4];
    const void*   users    = d_in[5];
    const void*   items    = d_in[6];
    float4*       out      = (float4*)d_out;

    const int SPMM_BLOCKS = (N_NODES / 2 * 32 + 255) / 256;   // 2 rows per warp
    const int OUT_BLOCKS  = (BATCH * 32 + 255) / 256;          // 2 out rows per warp

    k_prep<<<1 + CNT_BLOCKS, 256>>>((const unsigned*)users);
    k_conv_scatter<<<EW_BLOCKS + NNZ_BLOCKS, 256>>>(user_emb, item_emb,
                                                    adj_rows, adj_cols, adj_vals);
    k_spmm16<<<SPMM_BLOCKS, 256>>>(0);
    k_spmm16<<<SPMM_BLOCKS, 256>>>(1);
    k_fused_out<<<OUT_BLOCKS, 256>>>(users, items, user_emb, item_emb, out);
}

// round 13
// speedup vs baseline: 1.1964x; 1.0485x over previous
#include <cuda_runtime.h>
#include <cuda_fp16.h>
#include <cstdint>

#define N_USERS 100000
#define N_ITEMS 50000
#define N_NODES 150000
#define EMB     128
#define NNZ     1600000
#define BATCH   4096
#define CAP     64            /* bucket capacity per row; Poisson(10.7) -> safe */

#define TOTAL4   (N_NODES * EMB / 4)
#define EW_BLOCKS   ((TOTAL4 + 255) / 256)        /* 18750 convert blocks */
#define NNZ_BLOCKS  ((NNZ + 255) / 256)           /* 6250 scatter blocks  */
#define CNT_BLOCKS  ((N_NODES + 255) / 256)       /* 586 zeroing blocks   */

// ---------------- device scratch (no allocations allowed) ------------------
__device__ __half g_x16[N_NODES * EMB];        // fp16 concat(user_emb,item_emb)
__device__ __half g_h1 [N_NODES * EMB];        // layer 1 out (fp16)
__device__ __half g_h2 [N_NODES * EMB];        // layer 2 out (fp16)
__device__ int2   g_bucket[N_NODES * CAP];     // {col, float_bits(val)} per row
__device__ int    g_cnt[N_NODES];              // per-row edge count (cursor)
__device__ int    g_is64;

// ---------------------------------------------------------------------------
// Prep: block 0 detects index dtype; remaining blocks zero the edge cursors.
// ---------------------------------------------------------------------------
__global__ void k_prep(const unsigned* __restrict__ w) {
    if (blockIdx.x == 0) {
        __shared__ unsigned s;
        if (threadIdx.x == 0) s = 0u;
        __syncthreads();
        unsigned o = 0u;
        for (int i = 1 + 2 * threadIdx.x; i < BATCH; i += 2 * blockDim.x)
            o |= w[i];
        atomicOr(&s, o);
        __syncthreads();
        if (threadIdx.x == 0) g_is64 = (s == 0u) ? 1 : 0;
    } else {
        int i = (blockIdx.x - 1) * blockDim.x + threadIdx.x;
        if (i < N_NODES) g_cnt[i] = 0;
    }
}

// ---------------------------------------------------------------------------
// Fused convert + scatter (independent data; overlapped memory streams).
// ---------------------------------------------------------------------------
__global__ void k_conv_scatter(const float4* __restrict__ u,
                               const float4* __restrict__ it,
                               const int*   __restrict__ rows,
                               const int*   __restrict__ cols,
                               const float* __restrict__ vals) {
    if (blockIdx.x < EW_BLOCKS) {
        int i = blockIdx.x * blockDim.x + threadIdx.x;
        if (i >= TOTAL4) return;
        const int usplit = N_USERS * EMB / 4;
        float4 v = (i < usplit) ? __ldg(&u[i]) : __ldg(&it[i - usplit]);
        __half2 h0 = __floats2half2_rn(v.x, v.y);
        __half2 h1 = __floats2half2_rn(v.z, v.w);
        uint2 p;
        p.x = *(const unsigned*)&h0;
        p.y = *(const unsigned*)&h1;
        ((uint2*)g_x16)[i] = p;
    } else {
        int i = (blockIdx.x - EW_BLOCKS) * blockDim.x + threadIdx.x;
        if (i >= NNZ) return;
        int r = __ldg(&rows[i]);
        int p = atomicAdd(&g_cnt[r], 1);
        if (p < CAP)
            g_bucket[(size_t)r * CAP + p] =
                make_int2(__ldg(&cols[i]), __float_as_int(__ldg(&vals[i])));
    }
}

// ---------------------------------------------------------------------------
// SpMM (fp16 gather, fp32 accumulate): dst[row] = sum v * src16[col]
// Two rows per warp, 16 lanes/row, lane owns 8 dims (uint4 = 4 half2).
// Main loop: unguarded chunks of 4 edges — descriptor loads batched, then
// 4 independent gathers batched (explicit MLP), then the FMA block.
// which: 0 = x16 -> h1, 1 = h1 -> h2
// ---------------------------------------------------------------------------
__device__ __forceinline__ void edge_fma(float4& a0, float4& a1,
                                         float v, uint4 xv) {
    float2 f0 = __half22float2(*(const __half2*)&xv.x);
    float2 f1 = __half22float2(*(const __half2*)&xv.y);
    float2 f2 = __half22float2(*(const __half2*)&xv.z);
    float2 f3 = __half22float2(*(const __half2*)&xv.w);
    a0.x = fmaf(v, f0.x, a0.x);  a0.y = fmaf(v, f0.y, a0.y);
    a0.z = fmaf(v, f1.x, a0.z);  a0.w = fmaf(v, f1.y, a0.w);
    a1.x = fmaf(v, f2.x, a1.x);  a1.y = fmaf(v, f2.y, a1.y);
    a1.z = fmaf(v, f3.x, a1.z);  a1.w = fmaf(v, f3.y, a1.w);
}

__global__ void k_spmm16(int which) {
    int warp = (blockIdx.x * blockDim.x + threadIdx.x) >> 5;
    int lane = threadIdx.x & 31;
    int hid  = lane >> 4;
    int sub  = lane & 15;
    int row  = warp * 2 + hid;
    if (row >= N_NODES) return;

    const uint4* x = which ? (const uint4*)g_h1 : (const uint4*)g_x16;
    uint4*       y = which ? (uint4*)g_h2       : (uint4*)g_h1;

    int n = min(__ldg(&g_cnt[row]), CAP);
    const int2* eb = g_bucket + (size_t)row * CAP;

    float4 a0 = make_float4(0.f, 0.f, 0.f, 0.f);
    float4 a1 = make_float4(0.f, 0.f, 0.f, 0.f);

    int j = 0;
    for (; j + 4 <= n; j += 4) {
        int2 cv0 = __ldg(&eb[j]);
        int2 cv1 = __ldg(&eb[j + 1]);
        int2 cv2 = __ldg(&eb[j + 2]);
        int2 cv3 = __ldg(&eb[j + 3]);
        uint4 x0 = __ldg(x + (size_t)cv0.x * 16 + sub);
        uint4 x1 = __ldg(x + (size_t)cv1.x * 16 + sub);
        uint4 x2 = __ldg(x + (size_t)cv2.x * 16 + sub);
        uint4 x3 = __ldg(x + (size_t)cv3.x * 16 + sub);
        edge_fma(a0, a1, __int_as_float(cv0.y), x0);
        edge_fma(a0, a1, __int_as_float(cv1.y), x1);
        edge_fma(a0, a1, __int_as_float(cv2.y), x2);
        edge_fma(a0, a1, __int_as_float(cv3.y), x3);
    }
    for (; j < n; j++) {
        int2 cv = __ldg(&eb[j]);
        uint4 xv = __ldg(x + (size_t)cv.x * 16 + sub);
        edge_fma(a0, a1, __int_as_float(cv.y), xv);
    }

    __half2 h0 = __floats2half2_rn(a0.x, a0.y);
    __half2 h1 = __floats2half2_rn(a0.z, a0.w);
    __half2 h2 = __floats2half2_rn(a1.x, a1.y);
    __half2 h3 = __floats2half2_rn(a1.z, a1.w);
    uint4 o;
    o.x = *(const unsigned*)&h0;
    o.y = *(const unsigned*)&h1;
    o.z = *(const unsigned*)&h2;
    o.w = *(const unsigned*)&h3;
    y[(size_t)row * 16 + sub] = o;
}

// ---------------------------------------------------------------------------
// Fused layer-3 + mean + gather. Two output rows per warp, fp32 math.
// ---------------------------------------------------------------------------
__global__ void k_fused_out(const void* __restrict__ users,
                            const void* __restrict__ items,
                            const float4* __restrict__ uemb,
                            const float4* __restrict__ iemb,
                            float4* __restrict__ out) {
    int warp = (blockIdx.x * blockDim.x + threadIdx.x) >> 5;
    int lane = threadIdx.x & 31;
    int hid  = lane >> 4;
    int sub  = lane & 15;
    int r    = warp * 2 + hid;
    if (r >= 2 * BATCH) return;

    long long node;
    if (r < BATCH) {
        node = g_is64 ? ((const long long*)users)[r]
                      : (long long)((const int*)users)[r];
    } else {
        int j = r - BATCH;
        long long iv = g_is64 ? ((const long long*)items)[j]
                              : (long long)((const int*)items)[j];
        node = (long long)N_USERS + iv;
    }

    const uint4* h1 = (const uint4*)g_h1;
    const uint4* h2 = (const uint4*)g_h2;

    const float4* b0base = (node < N_USERS) ? (uemb + node * 32)
                                            : (iemb + (node - N_USERS) * 32);
    float4 a0 = __ldg(b0base + sub * 2);
    float4 a1 = __ldg(b0base + sub * 2 + 1);

    {
        uint4 a = __ldg(h1 + node * 16 + sub);
        uint4 b = __ldg(h2 + node * 16 + sub);
        float2 p;
        p = __half22float2(*(const __half2*)&a.x); a0.x += p.x; a0.y += p.y;
        p = __half22float2(*(const __half2*)&a.y); a0.z += p.x; a0.w += p.y;
        p = __half22float2(*(const __half2*)&a.z); a1.x += p.x; a1.y += p.y;
        p = __half22float2(*(const __half2*)&a.w); a1.z += p.x; a1.w += p.y;
        p = __half22float2(*(const __half2*)&b.x); a0.x += p.x; a0.y += p.y;
        p = __half22float2(*(const __half2*)&b.y); a0.z += p.x; a0.w += p.y;
        p = __half22float2(*(const __half2*)&b.z); a1.x += p.x; a1.y += p.y;
        p = __half22float2(*(const __half2*)&b.w); a1.z += p.x; a1.w += p.y;
    }

    int n = min(__ldg(&g_cnt[node]), CAP);
    const int2* eb = g_bucket + (size_t)node * CAP;
    int j = 0;
    for (; j + 4 <= n; j += 4) {
        int2 cv0 = __ldg(&eb[j]);
        int2 cv1 = __ldg(&eb[j + 1]);
        int2 cv2 = __ldg(&eb[j + 2]);
        int2 cv3 = __ldg(&eb[j + 3]);
        uint4 x0 = __ldg(h2 + (size_t)cv0.x * 16 + sub);
        uint4 x1 = __ldg(h2 + (size_t)cv1.x * 16 + sub);
        uint4 x2 = __ldg(h2 + (size_t)cv2.x * 16 + sub);
        uint4 x3 = __ldg(h2 + (size_t)cv3.x * 16 + sub);
        edge_fma(a0, a1, __int_as_float(cv0.y), x0);
        edge_fma(a0, a1, __int_as_float(cv1.y), x1);
        edge_fma(a0, a1, __int_as_float(cv2.y), x2);
        edge_fma(a0, a1, __int_as_float(cv3.y), x3);
    }
    for (; j < n; j++) {
        int2 cv = __ldg(&eb[j]);
        uint4 xv = __ldg(h2 + (size_t)cv.x * 16 + sub);
        edge_fma(a0, a1, __int_as_float(cv.y), xv);
    }

    a0.x *= 0.25f; a0.y *= 0.25f; a0.z *= 0.25f; a0.w *= 0.25f;
    a1.x *= 0.25f; a1.y *= 0.25f; a1.z *= 0.25f; a1.w *= 0.25f;
    out[(size_t)r * 32 + sub * 2]     = a0;
    out[(size_t)r * 32 + sub * 2 + 1] = a1;
}

// ---------------------------------------------------------------------------
extern "C" void kernel_launch(void* const* d_in, const int* in_sizes, int n_in,
                              void* d_out, int out_size) {
    const float4* user_emb = (const float4*)d_in[0];
    const float4* item_emb = (const float4*)d_in[1];
    const float*  adj_vals = (const float*)d_in[2];
    const int*    adj_rows = (const int*)d_in[3];
    const int*    adj_cols = (const int*)d_in[4];
    const void*   users    = d_in[5];
    const void*   items    = d_in[6];
    float4*       out      = (float4*)d_out;

    const int SPMM_BLOCKS = (N_NODES / 2 * 32 + 255) / 256;   // 2 rows per warp
    const int OUT_BLOCKS  = (BATCH * 32 + 255) / 256;          // 2 out rows per warp

    k_prep<<<1 + CNT_BLOCKS, 256>>>((const unsigned*)users);
    k_conv_scatter<<<EW_BLOCKS + NNZ_BLOCKS, 256>>>(user_emb, item_emb,
                                                    adj_rows, adj_cols, adj_vals);
    k_spmm16<<<SPMM_BLOCKS, 256>>>(0);
    k_spmm16<<<SPMM_BLOCKS, 256>>>(1);
    k_fused_out<<<OUT_BLOCKS, 256>>>(users, items, user_emb, item_emb, out);
}